// round 12
// baseline (speedup 1.0000x reference)
#include <cuda_runtime.h>
#include <math.h>

// MatchLoss: per src point (16384x3 f32), is the 2nd-nearest tgt within 1e-3?
// mv = (pd<1e-3)+1e-7, pd = ||src - tgt_2nd + 1e-6||; out = log(1+sum(exp(mv)))
//    = log(1 + (N-m)*e^eps + m*e^(1+eps)),  m = match count.
// Spatial hash, cell = 2.1e-3 >= 2*r_eff: the radius ball fits in the 2x2x2
// cell block picked by the point's half-cell position -> 8 probes/src, all
// batched (independent loads, one latency round). Chained buckets with
// gen-stamped heads (no table clear). Single kernel, 64 blocks (single wave):
// insert -> barrier arrive -> src setup (overlaps) -> barrier wait -> query.
#define NPTS      16384
#define HBITS     16
#define HSIZE     (1 << HBITS)
#define THREADS   256
#define NB        (NPTS / THREADS)     // 64 blocks, one thread per point

#define EPS_F     1e-7f
#define CELL_F    2.1e-3f
#define INV_CELL  (1.0f / CELL_F)
#define R2CUT     (1.05e-3f * 1.05e-3f)   // = (CELL/2)^2 coverage guarantee
#define RAD2      (1e-3f * 1e-3f)
#define BIG       3.402823466e+38f

__device__ unsigned long long g_head[HSIZE];   // (gen<<14)|idx ; stale gen = empty
__device__ int                g_next[NPTS];
__device__ long long          g_ckey[NPTS];
__device__ int                g_match = 0;
__device__ int                g_bar   = 0;
__device__ int                g_exit  = 0;
__device__ unsigned long long g_gen   = 1;     // bumped by last block each launch

__device__ __forceinline__ unsigned int cell_hash(int cx, int cy, int cz) {
    unsigned int h = (unsigned int)(cx * 73856093) ^
                     (unsigned int)(cy * 19349663) ^
                     (unsigned int)(cz * 83492791);
    return h & (HSIZE - 1);
}

__device__ __forceinline__ long long cell_key(int cx, int cy, int cz) {
    return (((long long)(cx + (1 << 20))) << 42) |
           (((long long)(cy + (1 << 20))) << 21) |
            ((long long)(cz + (1 << 20)));
}

__global__ __launch_bounds__(THREADS)
void ml_fused_kernel(const float* __restrict__ src, const float* __restrict__ tgt,
                     float* __restrict__ out) {
    __shared__ int swarp[THREADS / 32];
    const int tid  = threadIdx.x;
    const int lane = tid & 31;
    const int warp = tid >> 5;
    const int i    = blockIdx.x * THREADS + tid;   // 0..16383, one point each

    const unsigned long long gen = g_gen;          // consistent: set pre-launch

    // ---- Insert tgt point i (chained bucket, gen-stamped head, no clear) ----
    {
        const float x = tgt[3 * i + 0], y = tgt[3 * i + 1], z = tgt[3 * i + 2];
        const int cx = (int)floorf(x * INV_CELL);
        const int cy = (int)floorf(y * INV_CELL);
        const int cz = (int)floorf(z * INV_CELL);
        g_ckey[i] = cell_key(cx, cy, cz);
        const unsigned long long old =
            atomicExch(&g_head[cell_hash(cx, cy, cz)],
                       (gen << 14) | (unsigned long long)i);
        g_next[i] = ((old >> 14) == gen) ? (int)(old & 16383ULL) : -1;
    }
    __threadfence();      // make this thread's inserts globally visible
    __syncthreads();

    // ---- Barrier ARRIVE (release); spin deferred until after src setup ----
    if (tid == 0) atomicAdd(&g_bar, 1);

    // ---- Src-side setup overlaps other blocks' inserts + barrier ----
    const float px = src[3 * i + 0], py = src[3 * i + 1], pz = src[3 * i + 2];
    const float fx = px * INV_CELL, fy = py * INV_CELL, fz = pz * INV_CELL;
    const int cx = (int)floorf(fx);
    const int cy = (int)floorf(fy);
    const int cz = (int)floorf(fz);
    // base corner of the 2x2x2 block containing the radius ball
    const int bx = cx + ((fx - (float)cx >= 0.5f) ? 0 : -1);
    const int by = cy + ((fy - (float)cy >= 0.5f) ? 0 : -1);
    const int bz = cz + ((fz - (float)cz >= 0.5f) ? 0 : -1);

    long long    pkeys[8];
    unsigned int phash[8];
    #pragma unroll
    for (int p = 0; p < 8; ++p) {
        const int ccx = bx + (p >> 2);
        const int ccy = by + ((p >> 1) & 1);
        const int ccz = bz + (p & 1);
        pkeys[p] = cell_key(ccx, ccy, ccz);
        phash[p] = cell_hash(ccx, ccy, ccz);
    }

    // ---- Barrier WAIT (acquire) ----
    if (tid == 0) {
        while (*(volatile int*)&g_bar < NB) { }
        __threadfence();
    }
    __syncthreads();

    // ---- Query: 8 batched independent head loads (one latency round) ----
    unsigned long long heads[8];
    #pragma unroll
    for (int p = 0; p < 8; ++p)
        heads[p] = g_head[phash[p]];

    float d1 = BIG, d2 = BIG;
    #pragma unroll
    for (int p = 0; p < 8; ++p) {
        int e = ((heads[p] >> 14) == gen) ? (int)(heads[p] & 16383ULL) : -1;
        while (e >= 0) {                       // cells almost always empty/singleton
            if (g_ckey[e] == pkeys[p]) {
                const float ex = px - tgt[3 * e + 0];
                const float ey = py - tgt[3 * e + 1];
                const float ez = pz - tgt[3 * e + 2];
                const float dd = fmaf(ex, ex, fmaf(ey, ey, ez * ez));
                d2 = fminf(d2, fmaxf(d1, dd));
                d1 = fminf(d1, dd);
            }
            e = g_next[e];
        }
    }

    int m = 0;
    if (d2 <= R2CUT) {
        // Rare exact path: rescan the 8 cells tracking coords, apply the
        // reference pd test (componentwise +1e-6 before the norm).
        float e1 = BIG, e2 = BIG;
        float q1x = 0, q1y = 0, q1z = 0, q2x = 0, q2y = 0, q2z = 0;
        for (int p = 0; p < 8; ++p) {
            int e = ((heads[p] >> 14) == gen) ? (int)(heads[p] & 16383ULL) : -1;
            while (e >= 0) {
                if (g_ckey[e] == pkeys[p]) {
                    const float tx = tgt[3 * e + 0], ty = tgt[3 * e + 1], tz = tgt[3 * e + 2];
                    const float ex = px - tx, ey = py - ty, ez = pz - tz;
                    const float dd = fmaf(ex, ex, fmaf(ey, ey, ez * ez));
                    if (dd < e2) {
                        if (dd < e1) {
                            e2 = e1; q2x = q1x; q2y = q1y; q2z = q1z;
                            e1 = dd; q1x = tx;  q1y = ty;  q1z = tz;
                        } else {
                            e2 = dd; q2x = tx; q2y = ty; q2z = tz;
                        }
                    }
                }
                e = g_next[e];
            }
        }
        if (e2 <= R2CUT) {
            const float ex = px - q2x + 1e-6f;
            const float ey = py - q2y + 1e-6f;
            const float ez = pz - q2z + 1e-6f;
            if (fmaf(ex, ex, fmaf(ey, ey, ez * ez)) < RAD2) m = 1;
        }
    }

    // Deterministic integer reduction; one atomic per block (64 total)
    #pragma unroll
    for (int o = 16; o > 0; o >>= 1)
        m += __shfl_down_sync(0xFFFFFFFFu, m, o);
    if (lane == 0) swarp[warp] = m;
    __syncthreads();

    if (tid == 0) {
        int bs = 0;
        #pragma unroll
        for (int w = 0; w < THREADS / 32; ++w) bs += swarp[w];
        if (bs) atomicAdd(&g_match, bs);
        __threadfence();
        // Last block to exit finalizes and restores state for graph replay.
        const int e = atomicAdd(&g_exit, 1);
        if (e == NB - 1) {
            const int mm = *(volatile int*)&g_match;
            const float S = (float)(NPTS - mm) * expf(EPS_F)
                          + (float)mm * expf(1.0f + EPS_F);
            out[0] = logf(1.0f + S);   // softplus(logsumexp(mv))
            g_match = 0;
            g_bar   = 0;
            g_exit  = 0;
            g_gen   = gen + 1;         // invalidates all buckets for next launch
            __threadfence();
        }
    }
}

extern "C" void kernel_launch(void* const* d_in, const int* in_sizes, int n_in,
                              void* d_out, int out_size) {
    const float* src = (const float*)d_in[0];  // src_coords [16384, 3]
    const float* tgt = (const float*)d_in[1];  // tgt_coords [16384, 3]
    float* out = (float*)d_out;
    ml_fused_kernel<<<NB, THREADS>>>(src, tgt, out);
}

// round 13
// speedup vs baseline: 1.3893x; 1.3893x over previous
#include <cuda_runtime.h>
#include <math.h>

// MatchLoss: per src point (16384x3 f32), is the 2nd-nearest tgt within 1e-3?
// mv = (pd<1e-3)+1e-7, pd = ||src - tgt_2nd + 1e-6||; out = log(1+sum(exp(mv)))
//    = log(1 + (N-m)*e^eps + m*e^(1+eps)),  m = match count.
// Spatial hash, cell = 2.1e-3 >= 2*r_eff: the radius ball fits in the 2x2x2
// cell block picked by the point's half-cell position -> 8 probe cells/src.
// 8 threads per src point, ONE probe cell each (2 serial latency rounds:
// head, then batched chain data). Chained buckets, gen-stamped heads (no
// clear). Single kernel, 512 blocks (single wave), split arrive/wait barrier.
#define NPTS      16384
#define HBITS     16
#define HSIZE     (1 << HBITS)
#define QSPLIT    8
#define THREADS   256
#define NB        (NPTS * QSPLIT / THREADS)   // 512 blocks, single wave

#define EPS_F     1e-7f
#define CELL_F    2.1e-3f
#define INV_CELL  (1.0f / CELL_F)
#define R2CUT     (1.05e-3f * 1.05e-3f)   // = (CELL/2)^2 coverage guarantee
#define RAD2      (1e-3f * 1e-3f)
#define BIG       3.402823466e+38f

__device__ unsigned long long g_head[HSIZE];   // (gen<<14)|idx ; stale gen = empty
__device__ int                g_next[NPTS];
__device__ long long          g_ckey[NPTS];
__device__ int                g_match = 0;
__device__ int                g_bar   = 0;
__device__ int                g_exit  = 0;
__device__ unsigned long long g_gen   = 1;     // bumped by last block each launch

__device__ __forceinline__ unsigned int cell_hash(int cx, int cy, int cz) {
    unsigned int h = (unsigned int)(cx * 73856093) ^
                     (unsigned int)(cy * 19349663) ^
                     (unsigned int)(cz * 83492791);
    return h & (HSIZE - 1);
}

__device__ __forceinline__ long long cell_key(int cx, int cy, int cz) {
    return (((long long)(cx + (1 << 20))) << 42) |
           (((long long)(cy + (1 << 20))) << 21) |
            ((long long)(cz + (1 << 20)));
}

__global__ __launch_bounds__(THREADS)
void ml_fused_kernel(const float* __restrict__ src, const float* __restrict__ tgt,
                     float* __restrict__ out) {
    __shared__ int swarp[THREADS / 32];
    const int tid  = threadIdx.x;
    const int lane = tid & 31;
    const int warp = tid >> 5;
    const int g    = blockIdx.x * THREADS + tid;   // 0..131071
    const int q    = g >> 3;                        // src index, 8 lanes each
    const int sub  = g & 7;                         // probe cell 0..7

    const unsigned long long gen = g_gen;           // consistent: set pre-launch

    // ---- Issue src loads immediately (overlap the insert round) ----
    const float px = src[3 * q + 0], py = src[3 * q + 1], pz = src[3 * q + 2];

    // ---- Insert tgt points (one lane in eight; gen-stamped heads, no clear) ----
    if (sub == 0) {
        const float x = tgt[3 * q + 0], y = tgt[3 * q + 1], z = tgt[3 * q + 2];
        const int cx = (int)floorf(x * INV_CELL);
        const int cy = (int)floorf(y * INV_CELL);
        const int cz = (int)floorf(z * INV_CELL);
        g_ckey[q] = cell_key(cx, cy, cz);
        const unsigned long long old =
            atomicExch(&g_head[cell_hash(cx, cy, cz)],
                       (gen << 14) | (unsigned long long)q);
        g_next[q] = ((old >> 14) == gen) ? (int)(old & 16383ULL) : -1;
    }
    __threadfence();
    __syncthreads();

    // ---- Barrier ARRIVE (release); spin deferred until after setup ----
    if (tid == 0) atomicAdd(&g_bar, 1);

    // ---- Probe setup overlaps other blocks' inserts + barrier ----
    const float fx = px * INV_CELL, fy = py * INV_CELL, fz = pz * INV_CELL;
    const int cx = (int)floorf(fx);
    const int cy = (int)floorf(fy);
    const int cz = (int)floorf(fz);
    // base corner of the 2x2x2 block containing the radius ball
    const int bx = cx + ((fx - (float)cx >= 0.5f) ? 0 : -1);
    const int by = cy + ((fy - (float)cy >= 0.5f) ? 0 : -1);
    const int bz = cz + ((fz - (float)cz >= 0.5f) ? 0 : -1);

    // This lane's single probe cell: bits of sub -> (x,y,z) corner offset
    const int ccx = bx + (sub >> 2);
    const int ccy = by + ((sub >> 1) & 1);
    const int ccz = bz + (sub & 1);
    const long long    pkey  = cell_key(ccx, ccy, ccz);
    const unsigned int phash = cell_hash(ccx, ccy, ccz);

    // ---- Barrier WAIT (acquire) ----
    if (tid == 0) {
        while (*(volatile int*)&g_bar < NB) { }
        __threadfence();
    }
    __syncthreads();

    // ---- Query: head round, then batched chain-data rounds ----
    const unsigned long long hw = g_head[phash];
    int e = ((hw >> 14) == gen) ? (int)(hw & 16383ULL) : -1;

    float d1 = BIG, d2 = BIG;
    while (e >= 0) {                 // almost always 0 or 1 iteration
        const long long k  = g_ckey[e];      // independent loads: one round
        const float    tx  = tgt[3 * e + 0];
        const float    ty  = tgt[3 * e + 1];
        const float    tz  = tgt[3 * e + 2];
        const int      nx  = g_next[e];
        if (k == pkey) {
            const float ex = px - tx, ey = py - ty, ez = pz - tz;
            const float dd = fmaf(ex, ex, fmaf(ey, ey, ez * ez));
            d2 = fminf(d2, fmaxf(d1, dd));
            d1 = fminf(d1, dd);
        }
        e = nx;
    }

    // Merge top-2 values across the 8 lanes of this src point
    #pragma unroll
    for (int o = 1; o <= 4; o <<= 1) {
        const float o1 = __shfl_xor_sync(0xFFFFFFFFu, d1, o);
        const float o2 = __shfl_xor_sync(0xFFFFFFFFu, d2, o);
        d2 = fminf(fmaxf(d1, o1), fminf(d2, o2));
        d1 = fminf(d1, o1);
    }

    int m = 0;
    if (sub == 0 && d2 <= R2CUT) {
        // Rare exact path: rescan the 8 cells tracking coords, apply the
        // reference pd test (componentwise +1e-6 before the norm).
        float e1 = BIG, e2 = BIG;
        float q1x = 0, q1y = 0, q1z = 0, q2x = 0, q2y = 0, q2z = 0;
        for (int p = 0; p < 8; ++p) {
            const int rx = bx + (p >> 2);
            const int ry = by + ((p >> 1) & 1);
            const int rz = bz + (p & 1);
            const long long pk = cell_key(rx, ry, rz);
            const unsigned long long hw2 = g_head[cell_hash(rx, ry, rz)];
            int ee = ((hw2 >> 14) == gen) ? (int)(hw2 & 16383ULL) : -1;
            while (ee >= 0) {
                if (g_ckey[ee] == pk) {
                    const float tx = tgt[3 * ee + 0], ty = tgt[3 * ee + 1], tz = tgt[3 * ee + 2];
                    const float ex = px - tx, ey = py - ty, ez = pz - tz;
                    const float dd = fmaf(ex, ex, fmaf(ey, ey, ez * ez));
                    if (dd < e2) {
                        if (dd < e1) {
                            e2 = e1; q2x = q1x; q2y = q1y; q2z = q1z;
                            e1 = dd; q1x = tx;  q1y = ty;  q1z = tz;
                        } else {
                            e2 = dd; q2x = tx; q2y = ty; q2z = tz;
                        }
                    }
                }
                ee = g_next[ee];
            }
        }
        if (e2 <= R2CUT) {
            const float ex = px - q2x + 1e-6f;
            const float ey = py - q2y + 1e-6f;
            const float ez = pz - q2z + 1e-6f;
            if (fmaf(ex, ex, fmaf(ey, ey, ez * ez)) < RAD2) m = 1;
        }
    }

    // Deterministic integer reduction; one atomic per block
    #pragma unroll
    for (int o = 16; o > 0; o >>= 1)
        m += __shfl_down_sync(0xFFFFFFFFu, m, o);
    if (lane == 0) swarp[warp] = m;
    __syncthreads();

    if (tid == 0) {
        int bs = 0;
        #pragma unroll
        for (int w = 0; w < THREADS / 32; ++w) bs += swarp[w];
        if (bs) atomicAdd(&g_match, bs);
        __threadfence();
        // Last block to exit finalizes and restores state for graph replay.
        const int e2 = atomicAdd(&g_exit, 1);
        if (e2 == NB - 1) {
            const int mm = *(volatile int*)&g_match;
            const float S = (float)(NPTS - mm) * expf(EPS_F)
                          + (float)mm * expf(1.0f + EPS_F);
            out[0] = logf(1.0f + S);   // softplus(logsumexp(mv))
            g_match = 0;
            g_bar   = 0;
            g_exit  = 0;
            g_gen   = gen + 1;         // invalidates all buckets for next launch
            __threadfence();
        }
    }
}

extern "C" void kernel_launch(void* const* d_in, const int* in_sizes, int n_in,
                              void* d_out, int out_size) {
    const float* src = (const float*)d_in[0];  // src_coords [16384, 3]
    const float* tgt = (const float*)d_in[1];  // tgt_coords [16384, 3]
    float* out = (float*)d_out;
    ml_fused_kernel<<<NB, THREADS>>>(src, tgt, out);
}

// round 14
// speedup vs baseline: 1.3995x; 1.0074x over previous
#include <cuda_runtime.h>
#include <math.h>

// MatchLoss: per src point (16384x3 f32), is the 2nd-nearest tgt within 1e-3?
// mv = (pd<1e-3)+1e-7, pd = ||src - tgt_2nd + 1e-6||; out = log(1+sum(exp(mv)))
//    = log(1 + (N-m)*e^eps + m*e^(1+eps)),  m = match count.
// Spatial hash, cell = 2.1e-3 >= 2*r_eff: radius ball fits in the 2x2x2 cell
// block picked by half-cell position -> 8 probe cells/src, 8 threads/src with
// ONE probe cell each (common case: one 8B head load, cell empty). Chained
// buckets, gen-stamped heads (no clear). Single kernel, 512 blocks (single
// wave), split arrive/wait barrier with writer-only release fences.
#define NPTS      16384
#define HBITS     16
#define HSIZE     (1 << HBITS)
#define QSPLIT    8
#define THREADS   256
#define NB        (NPTS * QSPLIT / THREADS)   // 512 blocks, single wave

#define EPS_F     1e-7f
#define CELL_F    2.1e-3f
#define INV_CELL  (1.0f / CELL_F)
#define R2CUT     (1.05e-3f * 1.05e-3f)   // = (CELL/2)^2 coverage guarantee
#define RAD2      (1e-3f * 1e-3f)
#define BIG       3.402823466e+38f

__device__ unsigned long long g_head[HSIZE];   // (gen<<14)|idx ; stale gen = empty
__device__ int                g_next[NPTS];
__device__ long long          g_ckey[NPTS];
__device__ int                g_match = 0;
__device__ int                g_bar   = 0;
__device__ int                g_exit  = 0;
__device__ unsigned long long g_gen   = 1;     // bumped by last block each launch

__device__ __forceinline__ unsigned int cell_hash(int cx, int cy, int cz) {
    unsigned int h = (unsigned int)(cx * 73856093) ^
                     (unsigned int)(cy * 19349663) ^
                     (unsigned int)(cz * 83492791);
    return h & (HSIZE - 1);
}

__device__ __forceinline__ long long cell_key(int cx, int cy, int cz) {
    return (((long long)(cx + (1 << 20))) << 42) |
           (((long long)(cy + (1 << 20))) << 21) |
            ((long long)(cz + (1 << 20)));
}

__global__ __launch_bounds__(THREADS)
void ml_fused_kernel(const float* __restrict__ src, const float* __restrict__ tgt,
                     float* __restrict__ out) {
    __shared__ int swarp[THREADS / 32];
    const int tid  = threadIdx.x;
    const int lane = tid & 31;
    const int warp = tid >> 5;
    const int g    = blockIdx.x * THREADS + tid;   // 0..131071
    const int q    = g >> 3;                        // src index, 8 lanes each
    const int sub  = g & 7;                         // probe cell 0..7

    const unsigned long long gen = g_gen;           // consistent: set pre-launch

    // ---- Issue src loads immediately (overlap the insert round) ----
    const float px = src[3 * q + 0], py = src[3 * q + 1], pz = src[3 * q + 2];

    // ---- Insert tgt points (one lane in eight); writers fence own stores ----
    if (sub == 0) {
        const float x = tgt[3 * q + 0], y = tgt[3 * q + 1], z = tgt[3 * q + 2];
        const int cx = (int)floorf(x * INV_CELL);
        const int cy = (int)floorf(y * INV_CELL);
        const int cz = (int)floorf(z * INV_CELL);
        g_ckey[q] = cell_key(cx, cy, cz);
        const unsigned long long old =
            atomicExch(&g_head[cell_hash(cx, cy, cz)],
                       (gen << 14) | (unsigned long long)q);
        g_next[q] = ((old >> 14) == gen) ? (int)(old & 16383ULL) : -1;
        __threadfence();           // release this writer's inserts
    }
    __syncthreads();

    // ---- Barrier ARRIVE (release); spin deferred until after setup ----
    if (tid == 0) atomicAdd(&g_bar, 1);

    // ---- Probe setup overlaps other blocks' inserts + barrier ----
    const float fx = px * INV_CELL, fy = py * INV_CELL, fz = pz * INV_CELL;
    const int cx = (int)floorf(fx);
    const int cy = (int)floorf(fy);
    const int cz = (int)floorf(fz);
    // base corner of the 2x2x2 block containing the radius ball
    const int bx = cx + ((fx - (float)cx >= 0.5f) ? 0 : -1);
    const int by = cy + ((fy - (float)cy >= 0.5f) ? 0 : -1);
    const int bz = cz + ((fz - (float)cz >= 0.5f) ? 0 : -1);

    // This lane's single probe cell: bits of sub -> (x,y,z) corner offset
    const int ccx = bx + (sub >> 2);
    const int ccy = by + ((sub >> 1) & 1);
    const int ccz = bz + (sub & 1);
    const long long    pkey  = cell_key(ccx, ccy, ccz);
    const unsigned int phash = cell_hash(ccx, ccy, ccz);

    // ---- Barrier WAIT (acquire), with backoff to unclog the counter ----
    if (tid == 0) {
        while (*(volatile int*)&g_bar < NB) { __nanosleep(64); }
        __threadfence();
    }
    __syncthreads();

    // ---- Query: one head load; chains almost never occupied ----
    const unsigned long long hw = g_head[phash];
    int e = ((hw >> 14) == gen) ? (int)(hw & 16383ULL) : -1;

    float d1 = BIG, d2 = BIG;
    while (e >= 0) {                 // almost always 0 iterations
        const long long k  = g_ckey[e];      // independent loads: one round
        const float    tx  = tgt[3 * e + 0];
        const float    ty  = tgt[3 * e + 1];
        const float    tz  = tgt[3 * e + 2];
        const int      nx  = g_next[e];
        if (k == pkey) {
            const float ex = px - tx, ey = py - ty, ez = pz - tz;
            const float dd = fmaf(ex, ex, fmaf(ey, ey, ez * ez));
            d2 = fminf(d2, fmaxf(d1, dd));
            d1 = fminf(d1, dd);
        }
        e = nx;
    }

    // Merge top-2 values across the 8 lanes of this src point
    #pragma unroll
    for (int o = 1; o <= 4; o <<= 1) {
        const float o1 = __shfl_xor_sync(0xFFFFFFFFu, d1, o);
        const float o2 = __shfl_xor_sync(0xFFFFFFFFu, d2, o);
        d2 = fminf(fmaxf(d1, o1), fminf(d2, o2));
        d1 = fminf(d1, o1);
    }

    int m = 0;
    if (sub == 0 && d2 <= R2CUT) {
        // Rare exact path: rescan the 8 cells tracking coords, apply the
        // reference pd test (componentwise +1e-6 before the norm).
        float e1 = BIG, e2 = BIG;
        float q1x = 0, q1y = 0, q1z = 0, q2x = 0, q2y = 0, q2z = 0;
        for (int p = 0; p < 8; ++p) {
            const int rx = bx + (p >> 2);
            const int ry = by + ((p >> 1) & 1);
            const int rz = bz + (p & 1);
            const long long pk = cell_key(rx, ry, rz);
            const unsigned long long hw2 = g_head[cell_hash(rx, ry, rz)];
            int ee = ((hw2 >> 14) == gen) ? (int)(hw2 & 16383ULL) : -1;
            while (ee >= 0) {
                if (g_ckey[ee] == pk) {
                    const float tx = tgt[3 * ee + 0], ty = tgt[3 * ee + 1], tz = tgt[3 * ee + 2];
                    const float ex = px - tx, ey = py - ty, ez = pz - tz;
                    const float dd = fmaf(ex, ex, fmaf(ey, ey, ez * ez));
                    if (dd < e2) {
                        if (dd < e1) {
                            e2 = e1; q2x = q1x; q2y = q1y; q2z = q1z;
                            e1 = dd; q1x = tx;  q1y = ty;  q1z = tz;
                        } else {
                            e2 = dd; q2x = tx; q2y = ty; q2z = tz;
                        }
                    }
                }
                ee = g_next[ee];
            }
        }
        if (e2 <= R2CUT) {
            const float ex = px - q2x + 1e-6f;
            const float ey = py - q2y + 1e-6f;
            const float ez = pz - q2z + 1e-6f;
            if (fmaf(ex, ex, fmaf(ey, ey, ez * ez)) < RAD2) m = 1;
        }
    }

    // Deterministic integer reduction; one atomic per block
    #pragma unroll
    for (int o = 16; o > 0; o >>= 1)
        m += __shfl_down_sync(0xFFFFFFFFu, m, o);
    if (lane == 0) swarp[warp] = m;
    __syncthreads();

    if (tid == 0) {
        int bs = 0;
        #pragma unroll
        for (int w = 0; w < THREADS / 32; ++w) bs += swarp[w];
        if (bs) atomicAdd(&g_match, bs);
        __threadfence();
        // Last block to exit finalizes and restores state for graph replay.
        const int e2 = atomicAdd(&g_exit, 1);
        if (e2 == NB - 1) {
            const int mm = *(volatile int*)&g_match;
            const float S = (float)(NPTS - mm) * expf(EPS_F)
                          + (float)mm * expf(1.0f + EPS_F);
            out[0] = logf(1.0f + S);   // softplus(logsumexp(mv))
            g_match = 0;
            g_bar   = 0;
            g_exit  = 0;
            g_gen   = gen + 1;         // invalidates all buckets for next launch
            __threadfence();
        }
    }
}

extern "C" void kernel_launch(void* const* d_in, const int* in_sizes, int n_in,
                              void* d_out, int out_size) {
    const float* src = (const float*)d_in[0];  // src_coords [16384, 3]
    const float* tgt = (const float*)d_in[1];  // tgt_coords [16384, 3]
    float* out = (float*)d_out;
    ml_fused_kernel<<<NB, THREADS>>>(src, tgt, out);
}